// round 16
// baseline (speedup 1.0000x reference)
#include <cuda_runtime.h>
#include <cuda_fp16.h>
#include <math.h>

#define D        64
#define MAXN     100000          // nodes per type (fixed by problem)
#define SLOTS    128             // max degree capacity (mean 40, sigma 6.3 -> P(>=128)~1e-30)
#define NBUCKET  (2 * MAXN)      // 0..N-1: iu edges (-> out[0]); N..2N-1: ui edges (-> out[1])
#define NH2      (MAXN * D / 2)  // half2 elements per feature table

// static device scratch (allocation-free; __device__ globals zero-initialized).
// record int2 = { src byte-offset into fp16 table (src<<7), w as f32 bits }.
// Slots >= cnt are never written (deterministic work each run) -> stay zero
// {off=0, w=0.0f}; accum rounds cnt up to 8 and needs no per-edge predication.
__device__ int     g_cnt[NBUCKET];                      // per-bucket counts / cursors
__device__ int2    g_rec[(size_t)NBUCKET * SLOTS];      // packed records (205 MB)
__device__ __half2 g_item_h[NH2];                       // fp16 mirror of item_feat (12.8 MB)
__device__ __half2 g_user_h[NH2];                       // fp16 mirror of user_feat (12.8 MB)

__device__ __forceinline__ unsigned h2_as_u32(__half2 h) {
    return ((unsigned)__half_as_ushort(__high2half(h)) << 16) |
            (unsigned)__half_as_ushort(__low2half(h));
}

// ---------------------------------------------------------------------------
// 0) zero the bucket counters (fills depend only on this tiny kernel)
// ---------------------------------------------------------------------------
__global__ void zero_cnt_kernel() {
    int i = blockIdx.x * blockDim.x + threadIdx.x;
    if (i < NBUCKET) g_cnt[i] = 0;
}

// ---------------------------------------------------------------------------
// 1) fp16 mirrors (on s2, concurrent with both fills)
// ---------------------------------------------------------------------------
__global__ void convert_kernel(const float4* __restrict__ item_feat,
                               const float4* __restrict__ user_feat) {
    int i = blockIdx.x * blockDim.x + threadIdx.x;          // over NH2/2 float4s
    if (i < NH2 / 2) {
        float4 a = __ldg(item_feat + i);
        float4 b = __ldg(user_feat + i);
        __half2 a0 = __floats2half2_rn(a.x, a.y), a1 = __floats2half2_rn(a.z, a.w);
        __half2 b0 = __floats2half2_rn(b.x, b.y), b1 = __floats2half2_rn(b.z, b.w);
        reinterpret_cast<uint2*>(g_item_h)[i] = make_uint2(h2_as_u32(a0), h2_as_u32(a1));
        reinterpret_cast<uint2*>(g_user_h)[i] = make_uint2(h2_as_u32(b0), h2_as_u32(b1));
    }
}

// ---------------------------------------------------------------------------
// 2) bucket edges by destination; record carries pre-shifted byte offset so
//    accum does zero decode work. Both fills are latency-bound sleepers
//    (issue ~3%) so they co-run nearly for free:
//    fill_dir0: flat grid on main. fill_dir1: persistent grid on s3, launched
//    at t~0 so it hides under fill0 AND accum0.
// ---------------------------------------------------------------------------
__global__ void fill_dir0_kernel(const int* __restrict__ src,
                                 const int* __restrict__ dst,
                                 const float* __restrict__ norm, int n_edges) {
    int t = blockIdx.x * blockDim.x + threadIdx.x;
    if (t >= n_edges) return;
    int   s = __ldg(src + t);
    int   b = __ldg(dst + t);
    float w = __ldg(norm + t);
    int pos = atomicAdd(&g_cnt[b], 1);
    if (pos < SLOTS)
        g_rec[(size_t)b * SLOTS + pos] = make_int2(s << 7, __float_as_int(w));
}

__global__ void fill_dir1_kernel(const int* __restrict__ src,
                                 const int* __restrict__ dst,
                                 const float* __restrict__ norm, int n_edges) {
    int stride = gridDim.x * blockDim.x;
    for (int t = blockIdx.x * blockDim.x + threadIdx.x; t < n_edges; t += stride) {
        int   s = __ldg(src + t);
        int   b = MAXN + __ldg(dst + t);
        float w = __ldg(norm + t);
        int pos = atomicAdd(&g_cnt[b], 1);
        if (pos < SLOTS)
            g_rec[(size_t)b * SLOTS + pos] = make_int2(s << 7, __float_as_int(w));
    }
}

// ---------------------------------------------------------------------------
// 3) one warp per bucket: {byte_off, w_f32} records, no per-edge predication,
//    8 independent fp16 gathers per iteration, fused L2 normalize + store.
// ---------------------------------------------------------------------------
__device__ __forceinline__ void accum_body(float* __restrict__ out,
                                           int bucket_base, int n_buckets,
                                           const __half2* __restrict__ feat) {
    int gi   = (blockIdx.x * blockDim.x + threadIdx.x) >> 5;
    int lane = threadIdx.x & 31;
    if (gi >= n_buckets) return;
    int g = bucket_base + gi;

    int cnt  = g_cnt[g];                 // <= SLOTS by construction
    int cnt8 = (cnt + 7) & ~7;           // padded slots: off=0, w=0.0f
    const uint4* base4 = reinterpret_cast<const uint4*>(&g_rec[(size_t)g * SLOTS]);
    const char*  tbl   = reinterpret_cast<const char*>(feat) + lane * 4;

    float accx = 0.f, accy = 0.f;
    for (int e = 0; e < cnt8; e += 8) {
        uint4 a = __ldg(base4 + (e >> 1) + 0);   // 2 records each
        uint4 b = __ldg(base4 + (e >> 1) + 1);
        uint4 c = __ldg(base4 + (e >> 1) + 2);
        uint4 d = __ldg(base4 + (e >> 1) + 3);

        // 8 independent coalesced 128B gathers
        __half2 f0 = *reinterpret_cast<const __half2*>(tbl + a.x);
        __half2 f1 = *reinterpret_cast<const __half2*>(tbl + a.z);
        __half2 f2 = *reinterpret_cast<const __half2*>(tbl + b.x);
        __half2 f3 = *reinterpret_cast<const __half2*>(tbl + b.z);
        __half2 f4 = *reinterpret_cast<const __half2*>(tbl + c.x);
        __half2 f5 = *reinterpret_cast<const __half2*>(tbl + c.z);
        __half2 f6 = *reinterpret_cast<const __half2*>(tbl + d.x);
        __half2 f7 = *reinterpret_cast<const __half2*>(tbl + d.z);

        float2 v;
        float w0 = __int_as_float(a.y), w1 = __int_as_float(a.w);
        float w2 = __int_as_float(b.y), w3 = __int_as_float(b.w);
        float w4 = __int_as_float(c.y), w5 = __int_as_float(c.w);
        float w6 = __int_as_float(d.y), w7 = __int_as_float(d.w);

        v = __half22float2(f0); accx += w0 * v.x; accy += w0 * v.y;
        v = __half22float2(f1); accx += w1 * v.x; accy += w1 * v.y;
        v = __half22float2(f2); accx += w2 * v.x; accy += w2 * v.y;
        v = __half22float2(f3); accx += w3 * v.x; accy += w3 * v.y;
        v = __half22float2(f4); accx += w4 * v.x; accy += w4 * v.y;
        v = __half22float2(f5); accx += w5 * v.x; accy += w5 * v.y;
        v = __half22float2(f6); accx += w6 * v.x; accy += w6 * v.y;
        v = __half22float2(f7); accx += w7 * v.x; accy += w7 * v.y;
    }

    // fused L2 normalize over the 64-dim row held across the warp
    float ss = accx * accx + accy * accy;
    #pragma unroll
    for (int o = 16; o > 0; o >>= 1)
        ss += __shfl_xor_sync(0xffffffffu, ss, o);
    float inv = 1.0f / fmaxf(sqrtf(ss), 1e-12f);

    reinterpret_cast<float2*>(out)[(size_t)g * (D / 2) + lane] =
        make_float2(accx * inv, accy * inv);
}

__global__ void accum_dir0_kernel(float* __restrict__ out, int n_buckets) {
    accum_body(out, 0, n_buckets, g_item_h);
}
__global__ void accum_dir1_kernel(float* __restrict__ out, int n_buckets) {
    accum_body(out, MAXN, n_buckets, g_user_h);
}

// ---------------------------------------------------------------------------
// metadata order:
//   0 user_feat [N,64] f32     4 src_ui [E] i32
//   1 item_feat [N,64] f32     5 dst_ui [E] i32
//   2 norm_ui   [E,1]  f32     6 src_iu [E] i32
//   3 norm_iu   [E,1]  f32     7 dst_iu [E] i32
// out: [2, N, 64] f32 ; out[0] = l2norm(segsum(norm_iu*item_feat[src_iu] -> dst_iu))
//                       out[1] = l2norm(segsum(norm_ui*user_feat[src_ui] -> dst_ui))
//
// Schedule (3-way fork after zero; the two direction chains are independent):
//   main: zero -> evZ -> fill0(flat) -> wait(evC) accum0 -> wait(evB) accum1
//   s2:   wait(evZ) -> convert -> evC
//   s3:   wait(evZ) -> fill1(persistent 370) -> evB
// fill1 hides under fill0 AND accum0; convert hides under fill0.
// ---------------------------------------------------------------------------
extern "C" void kernel_launch(void* const* d_in, const int* in_sizes, int n_in,
                              void* d_out, int out_size) {
    const float* user_feat = (const float*)d_in[0];
    const float* item_feat = (const float*)d_in[1];
    const float* norm_ui   = (const float*)d_in[2];
    const float* norm_iu   = (const float*)d_in[3];
    const int*   src_ui    = (const int*)d_in[4];
    const int*   dst_ui    = (const int*)d_in[5];
    const int*   src_iu    = (const int*)d_in[6];
    const int*   dst_iu    = (const int*)d_in[7];

    float* out = (float*)d_out;

    const int n_nodes = in_sizes[0] / D;   // 100000
    const int n_edges = in_sizes[4];       // 4000000

    // lazy host-side resources (no device memory; identical work per call)
    static cudaStream_t s2 = nullptr, s3 = nullptr;
    static cudaEvent_t  evZ = nullptr, evB = nullptr, evC = nullptr;
    if (s2 == nullptr) {
        cudaStreamCreateWithFlags(&s2, cudaStreamNonBlocking);
        cudaStreamCreateWithFlags(&s3, cudaStreamNonBlocking);
        cudaEventCreateWithFlags(&evZ, cudaEventDisableTiming);
        cudaEventCreateWithFlags(&evB, cudaEventDisableTiming);
        cudaEventCreateWithFlags(&evC, cudaEventDisableTiming);
    }

    int eb = (n_edges + 255) / 256;
    int ab = (n_nodes * 32 + 255) / 256;
    int cthreads = NH2 / 2;

    // main: zero counters (first captured node); fork point
    zero_cnt_kernel<<<(NBUCKET + 255) / 256, 256>>>();
    cudaEventRecord(evZ, 0);

    // s2: fp16 mirrors (hides under fill0)
    cudaStreamWaitEvent(s2, evZ, 0);
    convert_kernel<<<(cthreads + 255) / 256, 256, 0, s2>>>(
        (const float4*)item_feat, (const float4*)user_feat);
    cudaEventRecord(evC, s2);

    // s3: persistent fill of direction 1 (hides under fill0 + accum0)
    cudaStreamWaitEvent(s3, evZ, 0);
    fill_dir1_kernel<<<370, 256, 0, s3>>>(src_ui, dst_ui, norm_ui, n_edges);
    cudaEventRecord(evB, s3);

    // main: fill direction 0, then accumulate direction 0
    fill_dir0_kernel<<<eb, 256>>>(src_iu, dst_iu, norm_iu, n_edges);
    cudaStreamWaitEvent(0, evC, 0);
    accum_dir0_kernel<<<ab, 256>>>(out, n_nodes);

    // join with fill1 chain, then accumulate direction 1
    cudaStreamWaitEvent(0, evB, 0);
    accum_dir1_kernel<<<ab, 256>>>(out, n_nodes);
}